// round 4
// baseline (speedup 1.0000x reference)
#include <cuda_runtime.h>

namespace {

constexpr int BATCH = 16;
constexpr int HH    = 512;
constexpr int WW    = 512;
constexpr int NT    = 256;                       // threads per block
constexpr int OUTPX = 118;                       // output pixels per block in W
constexpr int NBX   = (WW + OUTPX - 1) / OUTPX;  // 5
constexpr int RS    = 64;                        // rows per block
constexpr int NBY   = HH / RS;                   // 8
constexpr int NC    = 2 * OUTPX;                 // output float4 columns per block (236)

__device__ __forceinline__ float4 f4add(float4 a, float4 b) {
    return make_float4(a.x + b.x, a.y + b.y, a.z + b.z, a.w + b.w);
}
__device__ __forceinline__ float4 f4sub(float4 a, float4 b) {
    return make_float4(a.x - b.x, a.y - b.y, a.z - b.z, a.w - b.w);
}
__device__ __forceinline__ float4 f4fma(float4 a, float s, float4 c) {
    return make_float4(fmaf(a.x, s, c.x), fmaf(a.y, s, c.y),
                       fmaf(a.z, s, c.z), fmaf(a.w, s, c.w));
}

// one symmetric tap-pair of the vertical pass: u = row h+d, v = row h-d
__device__ __forceinline__ void vacc(const float4& u, const float4& v,
                                     float d, float d2,
                                     float4& S, float4& A, float4& B) {
    float4 p = f4add(u, v);
    float4 m = f4sub(u, v);
    S = f4add(S, p);
    A = f4fma(m, d, A);
    B = f4fma(p, d2, B);
}

__global__ void __launch_bounds__(NT)
curv_kernel(const float4* __restrict__ in, float4* __restrict__ out) {
    const int t  = threadIdx.x;
    const int bx = blockIdx.x, by = blockIdx.y, bz = blockIdx.z;

    const int ps   = bx * OUTPX;          // first output pixel of this block
    const int lp   = t >> 1;              // local pixel (0..127), 2 float4 per pixel
    const int half = t & 1;               // which float4 of the pixel (ch 0-3 / 4-7)
    const int gp   = ps - 5 + lp;         // global pixel column of this lane
    const bool colok = (gp >= 0) && (gp < WW);
    const int h0      = by * RS;
    const int imgbase = bz * HH;

    __shared__ float4 sv[2][3][NT];       // [row 0/1][A,B,S][column lane]

    const float4 zero = make_float4(0.f, 0.f, 0.f, 0.f);
    float4 ring[12];                      // rows h-5 .. h+6 for this column

    auto ld = [&](int r) -> float4 {
        if (colok && (unsigned)r < (unsigned)HH)
            return in[((imgbase + r) * WW + gp) * 2 + half];
        return zero;
    };

#pragma unroll
    for (int i = 0; i < 10; ++i) ring[i] = ld(h0 - 5 + i);

    for (int h = h0; h < h0 + RS; h += 2) {
        ring[10] = ld(h + 5);
        ring[11] = ld(h + 6);

        // vertical pass, rows h and h+1: S = box, A = sum d*x, B = sum d^2*x
        float4 S0 = ring[5], A0 = zero, B0 = zero;
        vacc(ring[6],  ring[4], 1.f,  1.f, S0, A0, B0);
        vacc(ring[7],  ring[3], 2.f,  4.f, S0, A0, B0);
        vacc(ring[8],  ring[2], 3.f,  9.f, S0, A0, B0);
        vacc(ring[9],  ring[1], 4.f, 16.f, S0, A0, B0);
        vacc(ring[10], ring[0], 5.f, 25.f, S0, A0, B0);

        float4 S1 = ring[6], A1 = zero, B1 = zero;
        vacc(ring[7],  ring[5], 1.f,  1.f, S1, A1, B1);
        vacc(ring[8],  ring[4], 2.f,  4.f, S1, A1, B1);
        vacc(ring[9],  ring[3], 3.f,  9.f, S1, A1, B1);
        vacc(ring[10], ring[2], 4.f, 16.f, S1, A1, B1);
        vacc(ring[11], ring[1], 5.f, 25.f, S1, A1, B1);

        sv[0][0][t] = A0; sv[0][1][t] = B0; sv[0][2][t] = S0;
        sv[1][0][t] = A1; sv[1][1][t] = B1; sv[1][2][t] = S1;

        // advance ring by 2 rows (register moves only)
#pragma unroll
        for (int i = 0; i < 10; ++i) ring[i] = ring[i + 2];

        __syncthreads();

        // horizontal pass: 236 lanes, each handles output float4 column c=t
        // for BOTH rows (2 items/thread, 472 items total = full coverage).
        if (t < NC) {
            const int c   = t;                 // output float4 column 0..235
            const int gpx = ps + (c >> 1);     // global output pixel
            if (gpx < WW) {
#pragma unroll
                for (int r = 0; r < 2; ++r) {
                    const float4* Ar = sv[r][0];
                    const float4* Br = sv[r][1];
                    const float4* Sr = sv[r][2];

                    // taps live at smem columns c + 2e, e = 0..10 (center e=5)
                    float4 ox = Ar[c], sx = Br[c];
#pragma unroll
                    for (int e = 1; e <= 10; ++e) {
                        ox = f4add(ox, Ar[c + 2 * e]);
                        sx = f4add(sx, Br[c + 2 * e]);
                    }

                    float4 oy = zero, sy = zero;   // center weight is 0
#pragma unroll
                    for (int k = 1; k <= 5; ++k) {
                        float4 u = Sr[c + 2 * (5 + k)];
                        float4 v = Sr[c + 2 * (5 - k)];
                        float4 p = f4add(u, v);
                        float4 m = f4sub(u, v);
                        oy = f4fma(m, (float)k,       oy);
                        sy = f4fma(p, (float)(k * k), sy);
                    }

                    float4 res;
                    res.x = 2.f * sqrtf(fmaf(ox.x, ox.x, oy.x * oy.x)) / (sx.x + sy.x + 1e-5f);
                    res.y = 2.f * sqrtf(fmaf(ox.y, ox.y, oy.y * oy.y)) / (sx.y + sy.y + 1e-5f);
                    res.z = 2.f * sqrtf(fmaf(ox.z, ox.z, oy.z * oy.z)) / (sx.z + sy.z + 1e-5f);
                    res.w = 2.f * sqrtf(fmaf(ox.w, ox.w, oy.w * oy.w)) / (sx.w + sy.w + 1e-5f);

                    out[((imgbase + h + r) * WW + gpx) * 2 + (c & 1)] = res;
                }
            }
        }
        __syncthreads();
    }
}

}  // namespace

extern "C" void kernel_launch(void* const* d_in, const int* in_sizes, int n_in,
                              void* d_out, int out_size) {
    const float4* in = (const float4*)d_in[0];
    float4* outp     = (float4*)d_out;
    dim3 grid(NBX, NBY, BATCH);
    curv_kernel<<<grid, NT>>>(in, outp);
}

// round 5
// speedup vs baseline: 1.4833x; 1.4833x over previous
#include <cuda_runtime.h>

namespace {

constexpr int BATCH = 16;
constexpr int HH    = 512;
constexpr int WW    = 512;
constexpr int NT    = 288;              // 9 warps
constexpr int OUTPX = 128;              // output pixels per block in W
constexpr int NBX   = 4;                // 4*128 = 512, exact cover
constexpr int RS    = 64;               // rows per block
constexpr int NBY   = HH / RS;          // 8
constexpr int RPI   = 4;                // rows per iteration
constexpr int KRUN  = 5;                // output pixels per horizontal run
constexpr int NRUNS = 26;               // ceil(128/5)
constexpr int NJ    = 138;              // input pixel columns (128 + 10 halo)
constexpr int JP    = 140;              // padded inner stride (f4): 140*16 = 2240 B, ≡64 mod 128
constexpr int SP    = 132;              // stage inner stride: 132*16 = 2112 B, ≡64 mod 128

constexpr int DATA_F4   = 3 * RPI * 2 * JP;   // A,B,S planes: 3360 f4
constexpr int STAGE_F4  = RPI * 2 * SP;       // 1056 f4
constexpr int SMEM_BYTES = (DATA_F4 + STAGE_F4) * 16;   // 70656 B

__device__ __forceinline__ float4 f4add(float4 a, float4 b) {
    return make_float4(a.x + b.x, a.y + b.y, a.z + b.z, a.w + b.w);
}
__device__ __forceinline__ float4 f4sub(float4 a, float4 b) {
    return make_float4(a.x - b.x, a.y - b.y, a.z - b.z, a.w - b.w);
}
__device__ __forceinline__ float4 f4fma(float4 a, float s, float4 c) {
    return make_float4(fmaf(a.x, s, c.x), fmaf(a.y, s, c.y),
                       fmaf(a.z, s, c.z), fmaf(a.w, s, c.w));
}

// one symmetric tap-pair of the vertical pass: u = row h+d, v = row h-d
__device__ __forceinline__ void vacc(const float4& u, const float4& v,
                                     float d, float d2,
                                     float4& S, float4& A, float4& B) {
    float4 p = f4add(u, v);
    float4 m = f4sub(u, v);
    S = f4add(S, p);
    A = f4fma(m, d, A);
    B = f4fma(p, d2, B);
}

__global__ void __launch_bounds__(NT, 2)
curv_kernel(const float4* __restrict__ in, float4* __restrict__ out) {
    extern __shared__ float4 sm[];
    float4* dA  = sm;                        // [RPI][2][JP]
    float4* dB  = sm + RPI * 2 * JP;
    float4* dS  = sm + 2 * RPI * 2 * JP;
    float4* stg = sm + DATA_F4;              // [RPI][2][SP]

    const int t  = threadIdx.x;
    const int bx = blockIdx.x, by = blockIdx.y, bz = blockIdx.z;
    const int ps   = bx * OUTPX;
    const int h0   = by * RS;
    const int base = bz * HH;

    // ---- vertical role: one (input pixel j, channel-half) column ----
    const int j    = t >> 1;                 // 0..143 (valid < NJ)
    const int half = t & 1;
    const int gp   = ps - 5 + j;             // global pixel column
    const bool vok = (t < 2 * NJ) && (gp >= 0) && (gp < WW);

    // ---- horizontal role: one run of KRUN output pixels ----
    const int grp   = t / NRUNS;             // (row*2 + half), valid < 8
    const int run   = t - grp * NRUNS;
    const bool hok  = t < 2 * RPI * NRUNS;   // 208 active

    const float4 zero = make_float4(0.f, 0.f, 0.f, 0.f);
    float4 ring[14];                         // raw rows h-5 .. h+8 for this column

    auto ld = [&](int r) -> float4 {
        if (vok && (unsigned)r < (unsigned)HH)
            return in[(base + r) * (WW * 2) + gp * 2 + half];
        return zero;
    };

#pragma unroll
    for (int i = 0; i < 10; ++i) ring[i] = ld(h0 - 5 + i);

    for (int h = h0; h < h0 + RS; h += RPI) {
#pragma unroll
        for (int i = 0; i < RPI; ++i) ring[10 + i] = ld(h + 5 + i);

        // ---- vertical pass: rows h .. h+3 -> S (box), A (Σd·x), B (Σd²·x) ----
        if (t < 2 * NJ) {
#pragma unroll
            for (int i = 0; i < RPI; ++i) {
                float4 S = ring[i + 5], A = zero, B = zero;
                vacc(ring[i + 6],  ring[i + 4], 1.f,  1.f, S, A, B);
                vacc(ring[i + 7],  ring[i + 3], 2.f,  4.f, S, A, B);
                vacc(ring[i + 8],  ring[i + 2], 3.f,  9.f, S, A, B);
                vacc(ring[i + 9],  ring[i + 1], 4.f, 16.f, S, A, B);
                vacc(ring[i + 10], ring[i + 0], 5.f, 25.f, S, A, B);
                const int o = (i * 2 + half) * JP + j;
                dA[o] = A; dB[o] = B; dS[o] = S;
            }
        }
#pragma unroll
        for (int i = 0; i < 10; ++i) ring[i] = ring[i + RPI];
        __syncthreads();

        // ---- horizontal pass: sliding-window recurrences over KRUN outputs ----
        if (hok) {
            const float4* A_ = dA + grp * JP;
            const float4* B_ = dB + grp * JP;
            const float4* S_ = dS + grp * JP;
            float4*       st = stg + grp * SP;
            const int p0 = run * KRUN;

            // prologue: full 11-tap window at p0
            float4 bA = zero, bB = zero, P = zero, L = zero, Q = zero;
#pragma unroll
            for (int e = 0; e <= 10; ++e) {
                float4 a = A_[p0 + e], b = B_[p0 + e], s = S_[p0 + e];
                bA = f4add(bA, a);
                bB = f4add(bB, b);
                P  = f4add(P, s);
                L  = f4fma(s, (float)e, L);
                Q  = f4fma(s, (float)(e * e), Q);
            }

#pragma unroll
            for (int s = 0; s < KRUN; ++s) {
                const int p = p0 + s;
                if (p >= OUTPX) break;
                if (s > 0) {
                    // slide window [p-1, p+9] -> [p, p+10]
                    float4 So = S_[p - 1], Sn = S_[p + 10];
                    float4 Ao = A_[p - 1], An = A_[p + 10];
                    float4 Bo = B_[p - 1], Bn = B_[p + 10];
                    // order matters: Q uses old L,P; L uses old P
                    Q = f4add(f4fma(L, -2.f, Q), P);
                    Q = f4sub(f4fma(Sn, 100.f, Q), So);
                    L = f4add(f4sub(L, P), So);
                    L = f4fma(Sn, 10.f, L);
                    P = f4add(f4sub(P, So), Sn);
                    bA = f4add(f4sub(bA, Ao), An);
                    bB = f4add(f4sub(bB, Bo), Bn);
                }
                const float4 oy = f4fma(P, -5.f, L);                    // L - 5P
                const float4 sy = f4fma(P, 25.f, f4fma(L, -10.f, Q));   // Q - 10L + 25P
                const float4 ox = bA, sx = bB;

                float4 res;
                res.x = 2.f * sqrtf(fmaf(ox.x, ox.x, oy.x * oy.x)) / (sx.x + sy.x + 1e-5f);
                res.y = 2.f * sqrtf(fmaf(ox.y, ox.y, oy.y * oy.y)) / (sx.y + sy.y + 1e-5f);
                res.z = 2.f * sqrtf(fmaf(ox.z, ox.z, oy.z * oy.z)) / (sx.z + sy.z + 1e-5f);
                res.w = 2.f * sqrtf(fmaf(ox.w, ox.w, oy.w * oy.w)) / (sx.w + sy.w + 1e-5f);
                st[p] = res;
            }
        }
        __syncthreads();

        // ---- coalesced output: 256 f4 per row, contiguous ----
        if (t < 2 * OUTPX) {
            const int ph = t >> 1, hf = t & 1;
#pragma unroll
            for (int rw = 0; rw < RPI; ++rw) {
                out[(base + h + rw) * (WW * 2) + ps * 2 + t] =
                    stg[(rw * 2 + hf) * SP + ph];
            }
        }
        __syncthreads();
    }
}

}  // namespace

extern "C" void kernel_launch(void* const* d_in, const int* in_sizes, int n_in,
                              void* d_out, int out_size) {
    const float4* in = (const float4*)d_in[0];
    float4* outp     = (float4*)d_out;
    static bool attr_set = false;   // idempotent attribute set (host-side, not captured)
    cudaFuncSetAttribute(curv_kernel, cudaFuncAttributeMaxDynamicSharedMemorySize,
                         SMEM_BYTES);
    dim3 grid(NBX, NBY, BATCH);
    curv_kernel<<<grid, NT, SMEM_BYTES>>>(in, outp);
}